// round 14
// baseline (speedup 1.0000x reference)
#include <cuda_runtime.h>
#include <cuda_bf16.h>

// CT parallel-beam forward projection.
// vol: [1, 32, 256, 256] f32   phis: [180] f32 (degrees)
// out: [1, 180, 32, 256] f32
//
// Pass 1: transpose + zero-pad volume to volT[261][261][32] (z innermost).
//         One (y,x) voxel column = 32 floats = one 128B line.
// Pass 2: one warp per (angle, col), 8 warps (= 8 adjacent cols) per block.
//         lane = tpair(1b)|xneighbor(1b)|zq(3b): each half-warp handles a
//         different t-sample; 2 x-neighbors across lanes; 2 y-neighbors via
//         a second LDG at +1 row with the y-lerp folded into the weights.
//         DEPTH-2 SOFTWARE PIPELINE over sample pairs: next stage's two
//         LDG.128 + weights issue before the current stage's 8 FMAs, giving
//         each warp a full loop body of load-to-use distance (needs the
//         64-reg budget from __launch_bounds__(256,4)).
//         Per-ray t-range trimming skips samples outside the volume (their
//         contribution is exactly zero under the reference's masking).

#define NZ      32
#define NXY     256
#define PAD_LO  2
#define PAD_HI  3
#define PDIM    (NXY + PAD_LO + PAD_HI)   // 261
#define N_T     384
#define N_ANG   180
#define ROWOFF  (PDIM * NZ / 4)           // +1 y-row in float4 units

// padded transposed volume: [PDIM][PDIM][32] floats = 8.72 MB
__device__ __align__(128) float g_volT[PDIM * PDIM * NZ];

// ---------------------------------------------------------------------------
// Pass 1: fill volT (zero border + transposed interior).
// ---------------------------------------------------------------------------
__global__ void fill_volT_kernel(const float* __restrict__ vol) {
    int idx = blockIdx.x * blockDim.x + threadIdx.x;
    const int total = PDIM * PDIM * NZ;
    if (idx >= total) return;
    int z   = idx & (NZ - 1);
    int pxy = idx >> 5;
    int px  = pxy % PDIM;
    int py  = pxy / PDIM;
    int x = px - PAD_LO;
    int y = py - PAD_LO;
    float v = 0.0f;
    if ((unsigned)x < (unsigned)NXY && (unsigned)y < (unsigned)NXY) {
        v = vol[(z << 16) + (y << 8) + x];   // vol[z][y][x]
    }
    g_volT[idx] = v;
}

// ---------------------------------------------------------------------------
// Pass 2: projection. blockDim = 256 (8 warps = 8 cols), grid = 180 * 32.
// __launch_bounds__(256, 4): 64-reg budget so the pipeline stays live.
// ---------------------------------------------------------------------------
__global__ void __launch_bounds__(256, 4)
project_kernel(const float* __restrict__ phis, float* __restrict__ out) {
    const int a    = blockIdx.x >> 5;                               // angle
    const int j    = ((blockIdx.x & 31) << 3) + (threadIdx.x >> 5); // detector col
    const int lane = threadIdx.x & 31;

    const float ang = phis[a] * 0.017453292519943295f;   // deg -> rad
    const float c = cosf(ang);
    const float s = sinf(ang);

    const float u   = (float)j - 127.5f;
    // ix = c*t - s*u + 127.5 ; iy = s*t + c*u + 127.5
    const float bx0 = fmaf(-s, u, 127.5f);
    const float by0 = fmaf( c, u, 127.5f);

    // ---- per-ray valid t-range: ix in (-1,256) AND iy in (-1,256) ----
    // (outside samples contribute exactly zero; boundary-exact samples have
    //  zero weight). Division by 0 -> +-inf, handled by min/max; never NaN.
    const float ta = (-1.0f  - bx0) / c;
    const float tb = (256.0f - bx0) / c;
    const float tc = (-1.0f  - by0) / s;
    const float td = (256.0f - by0) / s;
    const float tlo = fmaxf(fmaxf(fminf(ta, tb), fminf(tc, td)), -191.5f);
    const float thi = fminf(fminf(fmaxf(ta, tb), fmaxf(tc, td)),  191.5f);
    const int klo = (int)ceilf (tlo + 191.5f);   // warp-uniform
    const int khi = (int)floorf(thi + 191.5f);
    const int kcnt  = max(khi - klo + 1, 0);
    const int npair = kcnt >> 1;                 // full (k, k+1) pairs
    const int tail  = kcnt & 1;

    // lane decomposition
    const int h   = lane >> 4;        // 0/1: which t-sample of the pair
    const int dnx = (lane >> 3) & 1;  // x-neighbor
    const int zq  = lane & 7;         // z quarter -> z = 4*zq .. 4*zq+3

    // branch-free x-weight: wx = dnx ? fx : 1-fx
    const float sgx = dnx ? 1.0f : -1.0f;
    const float ofx = dnx ? 0.0f :  1.0f;
    const float hw  = h   ? 0.0f :  1.0f;   // tail mask for the h=1 sample

    // per-lane base pointer (PAD folded in; idx may be negative down to
    // -(PAD_LO*PDIM+PAD_LO), covered exactly)
    const float* __restrict__ basep =
        g_volT + ((PAD_LO * PDIM + PAD_LO) * NZ) + (dnx * NZ + zq * 4);

    float4 acc = make_float4(0.f, 0.f, 0.f, 0.f);
    // per-lane t of pair i: klo + 2*i + h  (all values exact in fp32)
    float tkl = (float)(klo + h) - 191.5f;

    // ---- depth-2 software pipeline over pairs --------------------------
    float4 v0c, v1c;            // in-flight loads for current stage
    float  w0c, w1c;            // weights for current stage

    if (npair > 0) {
        const float ix = fmaf(c, tkl, bx0);
        const float iy = fmaf(s, tkl, by0);
        const float fxf = floorf(ix), fyf = floorf(iy);
        const int idx = (int)fmaf(fyf, (float)PDIM, fxf);  // exact: |.| < 2^17
        const float4* p = reinterpret_cast<const float4*>(basep + idx * NZ);
        v0c = p[0];
        v1c = p[ROWOFF];
        const float wx = fmaf(sgx, ix - fxf, ofx);
        w1c = wx * (iy - fyf);
        w0c = wx - w1c;
    }

    #pragma unroll 2
    for (int i = 1; i < npair; ++i) {
        tkl += 2.0f;
        // ---- stage i: issue loads + weights (independent of v0c/v1c) ----
        const float ix = fmaf(c, tkl, bx0);
        const float iy = fmaf(s, tkl, by0);
        const float fxf = floorf(ix), fyf = floorf(iy);
        const int idx = (int)fmaf(fyf, (float)PDIM, fxf);
        const float4* p = reinterpret_cast<const float4*>(basep + idx * NZ);
        const float4 v0n = p[0];
        const float4 v1n = p[ROWOFF];
        const float wx = fmaf(sgx, ix - fxf, ofx);
        const float w1n = wx * (iy - fyf);
        const float w0n = wx - w1n;

        // ---- consume stage i-1 ----
        acc.x = fmaf(w0c, v0c.x, acc.x);
        acc.y = fmaf(w0c, v0c.y, acc.y);
        acc.z = fmaf(w0c, v0c.z, acc.z);
        acc.w = fmaf(w0c, v0c.w, acc.w);
        acc.x = fmaf(w1c, v1c.x, acc.x);
        acc.y = fmaf(w1c, v1c.y, acc.y);
        acc.z = fmaf(w1c, v1c.z, acc.z);
        acc.w = fmaf(w1c, v1c.w, acc.w);

        v0c = v0n; v1c = v1n; w0c = w0n; w1c = w1n;
    }

    if (npair > 0) {
        acc.x = fmaf(w0c, v0c.x, acc.x);
        acc.y = fmaf(w0c, v0c.y, acc.y);
        acc.z = fmaf(w0c, v0c.z, acc.z);
        acc.w = fmaf(w0c, v0c.w, acc.w);
        acc.x = fmaf(w1c, v1c.x, acc.x);
        acc.y = fmaf(w1c, v1c.y, acc.y);
        acc.z = fmaf(w1c, v1c.z, acc.z);
        acc.w = fmaf(w1c, v1c.w, acc.w);
    }

    // ---- tail: odd sample count ----------------------------------------
    if (tail) {
        // h=0 lane is k=khi (valid), h=1 lane is khi+1 -> weight forced 0
        // (one step of geometric overshoot lands in the zero pad).
        const float tkt = (float)(klo + 2 * npair + h) - 191.5f;   // exact
        const float ix = fmaf(c, tkt, bx0);
        const float iy = fmaf(s, tkt, by0);
        const float fxf = floorf(ix), fyf = floorf(iy);

        const int idx = (int)fmaf(fyf, (float)PDIM, fxf);
        const float4* p = reinterpret_cast<const float4*>(basep + idx * NZ);
        const float4 v0 = p[0];
        const float4 v1 = p[ROWOFF];

        const float wx = fmaf(sgx, ix - fxf, ofx) * hw;
        const float w1 = wx * (iy - fyf);
        const float w0 = wx - w1;

        acc.x = fmaf(w0, v0.x, acc.x);
        acc.y = fmaf(w0, v0.y, acc.y);
        acc.z = fmaf(w0, v0.z, acc.z);
        acc.w = fmaf(w0, v0.w, acc.w);
        acc.x = fmaf(w1, v1.x, acc.x);
        acc.y = fmaf(w1, v1.y, acc.y);
        acc.z = fmaf(w1, v1.z, acc.z);
        acc.w = fmaf(w1, v1.w, acc.w);
    }

    // reduce over x-neighbor (bit 3) and t-pair half (bit 4)
    acc.x += __shfl_xor_sync(0xFFFFFFFFu, acc.x, 8);
    acc.y += __shfl_xor_sync(0xFFFFFFFFu, acc.y, 8);
    acc.z += __shfl_xor_sync(0xFFFFFFFFu, acc.z, 8);
    acc.w += __shfl_xor_sync(0xFFFFFFFFu, acc.w, 8);
    acc.x += __shfl_xor_sync(0xFFFFFFFFu, acc.x, 16);
    acc.y += __shfl_xor_sync(0xFFFFFFFFu, acc.y, 16);
    acc.z += __shfl_xor_sync(0xFFFFFFFFu, acc.z, 16);
    acc.w += __shfl_xor_sync(0xFFFFFFFFu, acc.w, 16);

    if ((lane >> 3) == 0) {
        // out[a][z][j], z = 4*zq + {0,1,2,3}
        int base = (a * NZ + zq * 4) * NXY + j;
        out[base          ] = acc.x;
        out[base + NXY    ] = acc.y;
        out[base + 2 * NXY] = acc.z;
        out[base + 3 * NXY] = acc.w;
    }
}

// ---------------------------------------------------------------------------
extern "C" void kernel_launch(void* const* d_in, const int* in_sizes, int n_in,
                              void* d_out, int out_size) {
    const float* vol  = (const float*)d_in[0];   // [1,32,256,256]
    const float* phis = (const float*)d_in[1];   // [180]
    float* out = (float*)d_out;                  // [1,180,32,256]

    (void)in_sizes; (void)n_in; (void)out_size;

    const int totalT = PDIM * PDIM * NZ;
    fill_volT_kernel<<<(totalT + 255) / 256, 256>>>(vol);

    project_kernel<<<N_ANG * 32, 256>>>(phis, out);
}

// round 15
// speedup vs baseline: 1.0016x; 1.0016x over previous
#include <cuda_runtime.h>
#include <cuda_bf16.h>

// CT parallel-beam forward projection.
// vol: [1, 32, 256, 256] f32   phis: [180] f32 (degrees)
// out: [1, 180, 32, 256] f32
//
// Pass 1: transpose + zero-pad volume to volT[261][261][32] (z innermost).
//         One (y,x) voxel column = 32 floats = one 128B line.
// Pass 2: one warp per (angle, col), 8 warps (= 8 adjacent cols) per block.
//         lane = tpair(1b)|xneighbor(1b)|zq(3b): each half-warp handles a
//         different t-sample; 2 x-neighbors across lanes; 2 y-neighbors via
//         a second LDG at +1 row with the y-lerp folded into the weights.
//         DEPTH-2 SOFTWARE PIPELINE over sample pairs: next stage's two
//         LDG.128 + weights issue before the current stage's 8 FMAs, giving
//         each warp a full loop body of load-to-use distance (needs the
//         64-reg budget from __launch_bounds__(256,4)).
//         Per-ray t-range trimming skips samples outside the volume (their
//         contribution is exactly zero under the reference's masking).

#define NZ      32
#define NXY     256
#define PAD_LO  2
#define PAD_HI  3
#define PDIM    (NXY + PAD_LO + PAD_HI)   // 261
#define N_T     384
#define N_ANG   180
#define ROWOFF  (PDIM * NZ / 4)           // +1 y-row in float4 units

// padded transposed volume: [PDIM][PDIM][32] floats = 8.72 MB
__device__ __align__(128) float g_volT[PDIM * PDIM * NZ];

// ---------------------------------------------------------------------------
// Pass 1: fill volT (zero border + transposed interior).
// ---------------------------------------------------------------------------
__global__ void fill_volT_kernel(const float* __restrict__ vol) {
    int idx = blockIdx.x * blockDim.x + threadIdx.x;
    const int total = PDIM * PDIM * NZ;
    if (idx >= total) return;
    int z   = idx & (NZ - 1);
    int pxy = idx >> 5;
    int px  = pxy % PDIM;
    int py  = pxy / PDIM;
    int x = px - PAD_LO;
    int y = py - PAD_LO;
    float v = 0.0f;
    if ((unsigned)x < (unsigned)NXY && (unsigned)y < (unsigned)NXY) {
        v = vol[(z << 16) + (y << 8) + x];   // vol[z][y][x]
    }
    g_volT[idx] = v;
}

// ---------------------------------------------------------------------------
// Pass 2: projection. blockDim = 256 (8 warps = 8 cols), grid = 180 * 32.
// __launch_bounds__(256, 4): 64-reg budget so the pipeline stays live.
// ---------------------------------------------------------------------------
__global__ void __launch_bounds__(256, 4)
project_kernel(const float* __restrict__ phis, float* __restrict__ out) {
    const int a    = blockIdx.x >> 5;                               // angle
    const int j    = ((blockIdx.x & 31) << 3) + (threadIdx.x >> 5); // detector col
    const int lane = threadIdx.x & 31;

    const float ang = phis[a] * 0.017453292519943295f;   // deg -> rad
    const float c = cosf(ang);
    const float s = sinf(ang);

    const float u   = (float)j - 127.5f;
    // ix = c*t - s*u + 127.5 ; iy = s*t + c*u + 127.5
    const float bx0 = fmaf(-s, u, 127.5f);
    const float by0 = fmaf( c, u, 127.5f);

    // ---- per-ray valid t-range: ix in (-1,256) AND iy in (-1,256) ----
    // (outside samples contribute exactly zero; boundary-exact samples have
    //  zero weight). Division by 0 -> +-inf, handled by min/max; never NaN.
    const float ta = (-1.0f  - bx0) / c;
    const float tb = (256.0f - bx0) / c;
    const float tc = (-1.0f  - by0) / s;
    const float td = (256.0f - by0) / s;
    const float tlo = fmaxf(fmaxf(fminf(ta, tb), fminf(tc, td)), -191.5f);
    const float thi = fminf(fminf(fmaxf(ta, tb), fmaxf(tc, td)),  191.5f);
    const int klo = (int)ceilf (tlo + 191.5f);   // warp-uniform
    const int khi = (int)floorf(thi + 191.5f);
    const int kcnt  = max(khi - klo + 1, 0);
    const int npair = kcnt >> 1;                 // full (k, k+1) pairs
    const int tail  = kcnt & 1;

    // lane decomposition
    const int h   = lane >> 4;        // 0/1: which t-sample of the pair
    const int dnx = (lane >> 3) & 1;  // x-neighbor
    const int zq  = lane & 7;         // z quarter -> z = 4*zq .. 4*zq+3

    // branch-free x-weight: wx = dnx ? fx : 1-fx
    const float sgx = dnx ? 1.0f : -1.0f;
    const float ofx = dnx ? 0.0f :  1.0f;
    const float hw  = h   ? 0.0f :  1.0f;   // tail mask for the h=1 sample

    // per-lane base pointer (PAD folded in; idx may be negative down to
    // -(PAD_LO*PDIM+PAD_LO), covered exactly)
    const float* __restrict__ basep =
        g_volT + ((PAD_LO * PDIM + PAD_LO) * NZ) + (dnx * NZ + zq * 4);

    float4 acc = make_float4(0.f, 0.f, 0.f, 0.f);
    // per-lane t of pair i: klo + 2*i + h  (all values exact in fp32)
    float tkl = (float)(klo + h) - 191.5f;

    // ---- depth-2 software pipeline over pairs --------------------------
    float4 v0c, v1c;            // in-flight loads for current stage
    float  w0c, w1c;            // weights for current stage

    if (npair > 0) {
        const float ix = fmaf(c, tkl, bx0);
        const float iy = fmaf(s, tkl, by0);
        const float fxf = floorf(ix), fyf = floorf(iy);
        const int idx = (int)fmaf(fyf, (float)PDIM, fxf);  // exact: |.| < 2^17
        const float4* p = reinterpret_cast<const float4*>(basep + idx * NZ);
        v0c = p[0];
        v1c = p[ROWOFF];
        const float wx = fmaf(sgx, ix - fxf, ofx);
        w1c = wx * (iy - fyf);
        w0c = wx - w1c;
    }

    #pragma unroll 2
    for (int i = 1; i < npair; ++i) {
        tkl += 2.0f;
        // ---- stage i: issue loads + weights (independent of v0c/v1c) ----
        const float ix = fmaf(c, tkl, bx0);
        const float iy = fmaf(s, tkl, by0);
        const float fxf = floorf(ix), fyf = floorf(iy);
        const int idx = (int)fmaf(fyf, (float)PDIM, fxf);
        const float4* p = reinterpret_cast<const float4*>(basep + idx * NZ);
        const float4 v0n = p[0];
        const float4 v1n = p[ROWOFF];
        const float wx = fmaf(sgx, ix - fxf, ofx);
        const float w1n = wx * (iy - fyf);
        const float w0n = wx - w1n;

        // ---- consume stage i-1 ----
        acc.x = fmaf(w0c, v0c.x, acc.x);
        acc.y = fmaf(w0c, v0c.y, acc.y);
        acc.z = fmaf(w0c, v0c.z, acc.z);
        acc.w = fmaf(w0c, v0c.w, acc.w);
        acc.x = fmaf(w1c, v1c.x, acc.x);
        acc.y = fmaf(w1c, v1c.y, acc.y);
        acc.z = fmaf(w1c, v1c.z, acc.z);
        acc.w = fmaf(w1c, v1c.w, acc.w);

        v0c = v0n; v1c = v1n; w0c = w0n; w1c = w1n;
    }

    if (npair > 0) {
        acc.x = fmaf(w0c, v0c.x, acc.x);
        acc.y = fmaf(w0c, v0c.y, acc.y);
        acc.z = fmaf(w0c, v0c.z, acc.z);
        acc.w = fmaf(w0c, v0c.w, acc.w);
        acc.x = fmaf(w1c, v1c.x, acc.x);
        acc.y = fmaf(w1c, v1c.y, acc.y);
        acc.z = fmaf(w1c, v1c.z, acc.z);
        acc.w = fmaf(w1c, v1c.w, acc.w);
    }

    // ---- tail: odd sample count ----------------------------------------
    if (tail) {
        // h=0 lane is k=khi (valid), h=1 lane is khi+1 -> weight forced 0
        // (one step of geometric overshoot lands in the zero pad).
        const float tkt = (float)(klo + 2 * npair + h) - 191.5f;   // exact
        const float ix = fmaf(c, tkt, bx0);
        const float iy = fmaf(s, tkt, by0);
        const float fxf = floorf(ix), fyf = floorf(iy);

        const int idx = (int)fmaf(fyf, (float)PDIM, fxf);
        const float4* p = reinterpret_cast<const float4*>(basep + idx * NZ);
        const float4 v0 = p[0];
        const float4 v1 = p[ROWOFF];

        const float wx = fmaf(sgx, ix - fxf, ofx) * hw;
        const float w1 = wx * (iy - fyf);
        const float w0 = wx - w1;

        acc.x = fmaf(w0, v0.x, acc.x);
        acc.y = fmaf(w0, v0.y, acc.y);
        acc.z = fmaf(w0, v0.z, acc.z);
        acc.w = fmaf(w0, v0.w, acc.w);
        acc.x = fmaf(w1, v1.x, acc.x);
        acc.y = fmaf(w1, v1.y, acc.y);
        acc.z = fmaf(w1, v1.z, acc.z);
        acc.w = fmaf(w1, v1.w, acc.w);
    }

    // reduce over x-neighbor (bit 3) and t-pair half (bit 4)
    acc.x += __shfl_xor_sync(0xFFFFFFFFu, acc.x, 8);
    acc.y += __shfl_xor_sync(0xFFFFFFFFu, acc.y, 8);
    acc.z += __shfl_xor_sync(0xFFFFFFFFu, acc.z, 8);
    acc.w += __shfl_xor_sync(0xFFFFFFFFu, acc.w, 8);
    acc.x += __shfl_xor_sync(0xFFFFFFFFu, acc.x, 16);
    acc.y += __shfl_xor_sync(0xFFFFFFFFu, acc.y, 16);
    acc.z += __shfl_xor_sync(0xFFFFFFFFu, acc.z, 16);
    acc.w += __shfl_xor_sync(0xFFFFFFFFu, acc.w, 16);

    if ((lane >> 3) == 0) {
        // out[a][z][j], z = 4*zq + {0,1,2,3}
        int base = (a * NZ + zq * 4) * NXY + j;
        out[base          ] = acc.x;
        out[base + NXY    ] = acc.y;
        out[base + 2 * NXY] = acc.z;
        out[base + 3 * NXY] = acc.w;
    }
}

// ---------------------------------------------------------------------------
extern "C" void kernel_launch(void* const* d_in, const int* in_sizes, int n_in,
                              void* d_out, int out_size) {
    const float* vol  = (const float*)d_in[0];   // [1,32,256,256]
    const float* phis = (const float*)d_in[1];   // [180]
    float* out = (float*)d_out;                  // [1,180,32,256]

    (void)in_sizes; (void)n_in; (void)out_size;

    const int totalT = PDIM * PDIM * NZ;
    fill_volT_kernel<<<(totalT + 255) / 256, 256>>>(vol);

    project_kernel<<<N_ANG * 32, 256>>>(phis, out);
}

// round 16
// speedup vs baseline: 1.0204x; 1.0188x over previous
#include <cuda_runtime.h>
#include <cuda_bf16.h>

// CT parallel-beam forward projection.
// vol: [1, 32, 256, 256] f32   phis: [180] f32 (degrees)
// out: [1, 180, 32, 256] f32
//
// Pass 1: transpose + zero-pad volume to volT[261][261][32] (z innermost).
//         One (y,x) voxel column = 32 floats = one 128B line.
// Pass 2: one warp per (angle, col), 8 warps (= 8 adjacent cols) per block.
//         lane = tpair(1b)|xneighbor(1b)|zq(3b): each half-warp handles a
//         different t-sample; 2 x-neighbors across lanes; 2 y-neighbors via
//         a second LDG at +1 row with the y-lerp folded into the weights.
//         DEPTH-3 SOFTWARE PIPELINE (two stage buffers): stage i's two
//         LDG.128 issue two loop bodies before their consuming FMAs, so
//         each warp keeps 4 loads in flight. Requires the 64-reg budget
//         from __launch_bounds__(256,4) — do not lower it.
//         Per-ray t-range trimming skips samples outside the volume (their
//         contribution is exactly zero under the reference's masking).

#define NZ      32
#define NXY     256
#define PAD_LO  2
#define PAD_HI  3
#define PDIM    (NXY + PAD_LO + PAD_HI)   // 261
#define N_T     384
#define N_ANG   180
#define ROWOFF  (PDIM * NZ / 4)           // +1 y-row in float4 units

// padded transposed volume: [PDIM][PDIM][32] floats = 8.72 MB
__device__ __align__(128) float g_volT[PDIM * PDIM * NZ];

// ---------------------------------------------------------------------------
// Pass 1: fill volT (zero border + transposed interior).
// ---------------------------------------------------------------------------
__global__ void fill_volT_kernel(const float* __restrict__ vol) {
    int idx = blockIdx.x * blockDim.x + threadIdx.x;
    const int total = PDIM * PDIM * NZ;
    if (idx >= total) return;
    int z   = idx & (NZ - 1);
    int pxy = idx >> 5;
    int px  = pxy % PDIM;
    int py  = pxy / PDIM;
    int x = px - PAD_LO;
    int y = py - PAD_LO;
    float v = 0.0f;
    if ((unsigned)x < (unsigned)NXY && (unsigned)y < (unsigned)NXY) {
        v = vol[(z << 16) + (y << 8) + x];   // vol[z][y][x]
    }
    g_volT[idx] = v;
}

// issue one pipeline stage: compute coords/weights and launch both LDG.128
#define ISSUE(V0, V1, W0, W1) do {                                        \
    const float ix_ = fmaf(c, tkl, bx0);                                   \
    const float iy_ = fmaf(s, tkl, by0);                                   \
    const float fxf_ = floorf(ix_), fyf_ = floorf(iy_);                    \
    const int idx_ = (int)fmaf(fyf_, (float)PDIM, fxf_);                   \
    const float4* p_ = reinterpret_cast<const float4*>(basep + idx_ * NZ); \
    V0 = p_[0];                                                            \
    V1 = p_[ROWOFF];                                                       \
    const float wx_ = fmaf(sgx, ix_ - fxf_, ofx);                          \
    W1 = wx_ * (iy_ - fyf_);                                               \
    W0 = wx_ - W1;                                                         \
    tkl += 2.0f;                                                           \
} while (0)

// consume one pipeline stage: 8 FMAs into acc
#define CONSUME(V0, V1, W0, W1) do {                                       \
    acc.x = fmaf(W0, V0.x, acc.x);                                         \
    acc.y = fmaf(W0, V0.y, acc.y);                                         \
    acc.z = fmaf(W0, V0.z, acc.z);                                         \
    acc.w = fmaf(W0, V0.w, acc.w);                                         \
    acc.x = fmaf(W1, V1.x, acc.x);                                         \
    acc.y = fmaf(W1, V1.y, acc.y);                                         \
    acc.z = fmaf(W1, V1.z, acc.z);                                         \
    acc.w = fmaf(W1, V1.w, acc.w);                                         \
} while (0)

// ---------------------------------------------------------------------------
// Pass 2: projection. blockDim = 256 (8 warps = 8 cols), grid = 180 * 32.
// ---------------------------------------------------------------------------
__global__ void __launch_bounds__(256, 4)
project_kernel(const float* __restrict__ phis, float* __restrict__ out) {
    const int a    = blockIdx.x >> 5;                               // angle
    const int j    = ((blockIdx.x & 31) << 3) + (threadIdx.x >> 5); // detector col
    const int lane = threadIdx.x & 31;

    const float ang = phis[a] * 0.017453292519943295f;   // deg -> rad
    const float c = cosf(ang);
    const float s = sinf(ang);

    const float u   = (float)j - 127.5f;
    // ix = c*t - s*u + 127.5 ; iy = s*t + c*u + 127.5
    const float bx0 = fmaf(-s, u, 127.5f);
    const float by0 = fmaf( c, u, 127.5f);

    // ---- per-ray valid t-range: ix in (-1,256) AND iy in (-1,256) ----
    // (outside samples contribute exactly zero; boundary-exact samples have
    //  zero weight). Division by 0 -> +-inf, handled by min/max; never NaN.
    const float ta = (-1.0f  - bx0) / c;
    const float tb = (256.0f - bx0) / c;
    const float tc = (-1.0f  - by0) / s;
    const float td = (256.0f - by0) / s;
    const float tlo = fmaxf(fmaxf(fminf(ta, tb), fminf(tc, td)), -191.5f);
    const float thi = fminf(fminf(fmaxf(ta, tb), fmaxf(tc, td)),  191.5f);
    const int klo = (int)ceilf (tlo + 191.5f);   // warp-uniform
    const int khi = (int)floorf(thi + 191.5f);
    const int kcnt  = max(khi - klo + 1, 0);
    const int npair = kcnt >> 1;                 // full (k, k+1) pairs
    const int tail  = kcnt & 1;

    // lane decomposition
    const int h   = lane >> 4;        // 0/1: which t-sample of the pair
    const int dnx = (lane >> 3) & 1;  // x-neighbor
    const int zq  = lane & 7;         // z quarter -> z = 4*zq .. 4*zq+3

    // branch-free x-weight: wx = dnx ? fx : 1-fx
    const float sgx = dnx ? 1.0f : -1.0f;
    const float ofx = dnx ? 0.0f :  1.0f;
    const float hw  = h   ? 0.0f :  1.0f;   // tail mask for the h=1 sample

    // per-lane base pointer (PAD folded in; idx may be negative down to
    // -(PAD_LO*PDIM+PAD_LO), covered exactly)
    const float* __restrict__ basep =
        g_volT + ((PAD_LO * PDIM + PAD_LO) * NZ) + (dnx * NZ + zq * 4);

    float4 acc = make_float4(0.f, 0.f, 0.f, 0.f);
    // per-lane t of pair i: klo + 2*i + h  (all values exact in fp32)
    float tkl = (float)(klo + h) - 191.5f;

    // ---- depth-3 software pipeline over pairs (two stage buffers) -------
    float4 va0, va1, vb0, vb1;
    float  wa0, wa1, wb0, wb1;

    if (npair >= 2) {
        ISSUE(va0, va1, wa0, wa1);          // stage 0
        ISSUE(vb0, vb1, wb0, wb1);          // stage 1

        int i = 2;
        #pragma unroll 1
        for (; i + 2 <= npair; i += 2) {
            CONSUME(va0, va1, wa0, wa1);    // stage i-2
            ISSUE  (va0, va1, wa0, wa1);    // stage i
            CONSUME(vb0, vb1, wb0, wb1);    // stage i-1
            ISSUE  (vb0, vb1, wb0, wb1);    // stage i+1
        }
        if (i < npair) {                    // odd npair: one extra stage
            CONSUME(va0, va1, wa0, wa1);
            ISSUE  (va0, va1, wa0, wa1);    // stage npair-1
            CONSUME(vb0, vb1, wb0, wb1);
            CONSUME(va0, va1, wa0, wa1);
        } else {
            CONSUME(va0, va1, wa0, wa1);
            CONSUME(vb0, vb1, wb0, wb1);
        }
    } else if (npair == 1) {
        ISSUE  (va0, va1, wa0, wa1);
        CONSUME(va0, va1, wa0, wa1);
    }

    // ---- tail: odd sample count ----------------------------------------
    if (tail) {
        // h=0 lane is k=khi (valid), h=1 lane is khi+1 -> weight forced 0
        // (one step of geometric overshoot lands in the zero pad).
        // tkl has advanced exactly npair pairs: tkl == klo + 2*npair + h.
        const float ix = fmaf(c, tkl, bx0);
        const float iy = fmaf(s, tkl, by0);
        const float fxf = floorf(ix), fyf = floorf(iy);

        const int idx = (int)fmaf(fyf, (float)PDIM, fxf);
        const float4* p = reinterpret_cast<const float4*>(basep + idx * NZ);
        const float4 v0 = p[0];
        const float4 v1 = p[ROWOFF];

        const float wx = fmaf(sgx, ix - fxf, ofx) * hw;
        const float w1 = wx * (iy - fyf);
        const float w0 = wx - w1;

        acc.x = fmaf(w0, v0.x, acc.x);
        acc.y = fmaf(w0, v0.y, acc.y);
        acc.z = fmaf(w0, v0.z, acc.z);
        acc.w = fmaf(w0, v0.w, acc.w);
        acc.x = fmaf(w1, v1.x, acc.x);
        acc.y = fmaf(w1, v1.y, acc.y);
        acc.z = fmaf(w1, v1.z, acc.z);
        acc.w = fmaf(w1, v1.w, acc.w);
    }

    // reduce over x-neighbor (bit 3) and t-pair half (bit 4)
    acc.x += __shfl_xor_sync(0xFFFFFFFFu, acc.x, 8);
    acc.y += __shfl_xor_sync(0xFFFFFFFFu, acc.y, 8);
    acc.z += __shfl_xor_sync(0xFFFFFFFFu, acc.z, 8);
    acc.w += __shfl_xor_sync(0xFFFFFFFFu, acc.w, 8);
    acc.x += __shfl_xor_sync(0xFFFFFFFFu, acc.x, 16);
    acc.y += __shfl_xor_sync(0xFFFFFFFFu, acc.y, 16);
    acc.z += __shfl_xor_sync(0xFFFFFFFFu, acc.z, 16);
    acc.w += __shfl_xor_sync(0xFFFFFFFFu, acc.w, 16);

    if ((lane >> 3) == 0) {
        // out[a][z][j], z = 4*zq + {0,1,2,3}
        int base = (a * NZ + zq * 4) * NXY + j;
        out[base          ] = acc.x;
        out[base + NXY    ] = acc.y;
        out[base + 2 * NXY] = acc.z;
        out[base + 3 * NXY] = acc.w;
    }
}

// ---------------------------------------------------------------------------
extern "C" void kernel_launch(void* const* d_in, const int* in_sizes, int n_in,
                              void* d_out, int out_size) {
    const float* vol  = (const float*)d_in[0];   // [1,32,256,256]
    const float* phis = (const float*)d_in[1];   // [180]
    float* out = (float*)d_out;                  // [1,180,32,256]

    (void)in_sizes; (void)n_in; (void)out_size;

    const int totalT = PDIM * PDIM * NZ;
    fill_volT_kernel<<<(totalT + 255) / 256, 256>>>(vol);

    project_kernel<<<N_ANG * 32, 256>>>(phis, out);
}